// round 7
// baseline (speedup 1.0000x reference)
#include <cuda_runtime.h>
#include <math.h>

// Problem dims
#define B_    4
#define S_    2048
#define E_    2048
#define H_    16
#define HD_   128
#define M_    8192
#define NTOK  (B_ * S_)      // 8192
#define QKVLD (3 * E_)       // 6144

// ---------------- scratch (device globals; no allocations allowed) ----------
__device__ float g_h[(size_t)NTOK * E_];              //  64 MB  (LN1 out, reused for LN2 out)
__device__ float g_qkv[(size_t)NTOK * QKVLD];         // 192 MB
__device__ float g_scores[(size_t)B_ * H_ * S_ * S_]; //   1 GB
__device__ float g_attn[(size_t)NTOK * E_];           //  64 MB
__device__ float g_x2[(size_t)NTOK * E_];             //  64 MB  (x + attn residual)
__device__ float g_ff[(size_t)NTOK * M_];             // 256 MB

// ---------------- LayerNorm: one block per row (E=2048), 256 threads --------
__global__ __launch_bounds__(256)
void ln_kernel(const float* __restrict__ x, const float* __restrict__ gam,
               const float* __restrict__ bet, float* __restrict__ out)
{
    const int row = blockIdx.x;
    const int t = threadIdx.x;
    const float4* x4 = reinterpret_cast<const float4*>(x + (size_t)row * E_);
    float4 v0 = x4[t];
    float4 v1 = x4[t + 256];

    __shared__ float sh[256];
    float s = v0.x + v0.y + v0.z + v0.w + v1.x + v1.y + v1.z + v1.w;
    sh[t] = s;
    __syncthreads();
    #pragma unroll
    for (int o = 128; o > 0; o >>= 1) {
        if (t < o) sh[t] += sh[t + o];
        __syncthreads();
    }
    const float mu = sh[0] * (1.0f / (float)E_);
    __syncthreads();

    float d, sq = 0.f;
    d = v0.x - mu; sq += d * d;  d = v0.y - mu; sq += d * d;
    d = v0.z - mu; sq += d * d;  d = v0.w - mu; sq += d * d;
    d = v1.x - mu; sq += d * d;  d = v1.y - mu; sq += d * d;
    d = v1.z - mu; sq += d * d;  d = v1.w - mu; sq += d * d;
    sh[t] = sq;
    __syncthreads();
    #pragma unroll
    for (int o = 128; o > 0; o >>= 1) {
        if (t < o) sh[t] += sh[t + o];
        __syncthreads();
    }
    const float var = sh[0] * (1.0f / (float)E_);
    const float inv = rsqrtf(var + 1e-5f);

    const float4* g4 = reinterpret_cast<const float4*>(gam);
    const float4* b4 = reinterpret_cast<const float4*>(bet);
    float4 gg0 = g4[t], gg1 = g4[t + 256];
    float4 bb0 = b4[t], bb1 = b4[t + 256];

    float4 o0, o1;
    o0.x = (v0.x - mu) * inv * gg0.x + bb0.x;
    o0.y = (v0.y - mu) * inv * gg0.y + bb0.y;
    o0.z = (v0.z - mu) * inv * gg0.z + bb0.z;
    o0.w = (v0.w - mu) * inv * gg0.w + bb0.w;
    o1.x = (v1.x - mu) * inv * gg1.x + bb1.x;
    o1.y = (v1.y - mu) * inv * gg1.y + bb1.y;
    o1.z = (v1.z - mu) * inv * gg1.z + bb1.z;
    o1.w = (v1.w - mu) * inv * gg1.w + bb1.w;

    float4* out4 = reinterpret_cast<float4*>(out + (size_t)row * E_);
    out4[t]       = o0;
    out4[t + 256] = o1;
}

// ---------------- GELU (tanh approximation, matches reference) --------------
__device__ __forceinline__ float gelu_new(float x)
{
    float u = 0.7978845608028654f * (x + 0.044715f * x * x * x);
    return 0.5f * x * (1.0f + tanhf(u));
}

// ---------------- Generic SGEMM NN, 128x128x8 tiles, 8x8/thread -------------
// EPI: 1 = +bias ; 2 = gelu(acc+bias) ; 3 = acc+bias+res
template<int EPI>
__global__ __launch_bounds__(256)
void sgemm_nn(const float* __restrict__ A, int lda,
              const float* __restrict__ Bm, int ldb,
              float* __restrict__ C, int ldc,
              const float* __restrict__ bias,
              const float* __restrict__ res, int ldres,
              int K)
{
    __shared__ __align__(16) float As[8][128];
    __shared__ __align__(16) float Bs[8][128];

    const int t = threadIdx.x;
    const int row0 = blockIdx.y * 128;
    const int col0 = blockIdx.x * 128;

    const int arow = t >> 1;
    const int acol = (t & 1) * 4;
    const int brow = t >> 5;
    const int bcol = (t & 31) * 4;
    const int tx = t & 15;
    const int ty = t >> 4;

    const float* Ap = A + (size_t)(row0 + arow) * lda + acol;
    const float* Bp = Bm + (size_t)brow * ldb + col0 + bcol;

    float acc[8][8];
    #pragma unroll
    for (int i = 0; i < 8; i++) {
        #pragma unroll
        for (int j = 0; j < 8; j++) acc[i][j] = 0.f;
    }

    float4 av = *(const float4*)Ap;
    float4 bv = *(const float4*)Bp;

    for (int k0 = 0; k0 < K; k0 += 8) {
        __syncthreads();
        As[acol + 0][arow] = av.x;
        As[acol + 1][arow] = av.y;
        As[acol + 2][arow] = av.z;
        As[acol + 3][arow] = av.w;
        *(float4*)&Bs[brow][bcol] = bv;
        __syncthreads();
        if (k0 + 8 < K) {
            av = *(const float4*)(Ap + k0 + 8);
            bv = *(const float4*)(Bp + (size_t)(k0 + 8) * ldb);
        }
        #pragma unroll
        for (int k = 0; k < 8; k++) {
            float a[8], b[8];
            *(float4*)&a[0] = *(const float4*)&As[k][ty * 8];
            *(float4*)&a[4] = *(const float4*)&As[k][ty * 8 + 4];
            *(float4*)&b[0] = *(const float4*)&Bs[k][tx * 8];
            *(float4*)&b[4] = *(const float4*)&Bs[k][tx * 8 + 4];
            #pragma unroll
            for (int i = 0; i < 8; i++) {
                #pragma unroll
                for (int j = 0; j < 8; j++)
                    acc[i][j] = fmaf(a[i], b[j], acc[i][j]);
            }
        }
    }

    float bvv[8];
    *(float4*)&bvv[0] = *(const float4*)(bias + col0 + tx * 8);
    *(float4*)&bvv[4] = *(const float4*)(bias + col0 + tx * 8 + 4);

    #pragma unroll
    for (int i = 0; i < 8; i++) {
        const int r = row0 + ty * 8 + i;
        float v[8];
        #pragma unroll
        for (int j = 0; j < 8; j++) v[j] = acc[i][j] + bvv[j];
        if (EPI == 2) {
            #pragma unroll
            for (int j = 0; j < 8; j++) v[j] = gelu_new(v[j]);
        }
        if (EPI == 3) {
            float rv[8];
            const float* rp = res + (size_t)r * ldres + col0 + tx * 8;
            *(float4*)&rv[0] = *(const float4*)rp;
            *(float4*)&rv[4] = *(const float4*)(rp + 4);
            #pragma unroll
            for (int j = 0; j < 8; j++) v[j] += rv[j];
        }
        float* cp = C + (size_t)r * ldc + col0 + tx * 8;
        *(float4*)cp       = *(float4*)&v[0];
        *(float4*)(cp + 4) = *(float4*)&v[4];
    }
}

// ---------------- scores = scale * Q @ K^T, causal block-skipped -------------
// grid: (16 key-tiles, 16 q-tiles, B*H). NT gemm, K = HD = 128.
__global__ __launch_bounds__(256)
void attn_scores(const float* __restrict__ qkv, float* __restrict__ scores)
{
    const int bn = blockIdx.x, bm = blockIdx.y;
    if (bn > bm) return;  // strictly upper-triangle blocks never read
    const int z = blockIdx.z;
    const int b = z >> 4, hh = z & 15;

    const float* qb = qkv + (size_t)b * S_ * QKVLD + hh * HD_;       // Q part
    const float* kb = qb + E_;                                       // K part
    float* sb = scores + (size_t)z * S_ * S_;

    __shared__ __align__(16) float As[8][128];
    __shared__ __align__(16) float Bs[8][128];

    const int t = threadIdx.x;
    const int r = t >> 1;
    const int c4 = (t & 1) * 4;
    const int tx = t & 15;
    const int ty = t >> 4;
    const int row0 = bm * 128, col0 = bn * 128;

    const float* Ap = qb + (size_t)(row0 + r) * QKVLD + c4;
    const float* Bp = kb + (size_t)(col0 + r) * QKVLD + c4;

    float acc[8][8];
    #pragma unroll
    for (int i = 0; i < 8; i++) {
        #pragma unroll
        for (int j = 0; j < 8; j++) acc[i][j] = 0.f;
    }

    float4 av = *(const float4*)Ap;
    float4 bv = *(const float4*)Bp;

    for (int k0 = 0; k0 < HD_; k0 += 8) {
        __syncthreads();
        As[c4 + 0][r] = av.x; As[c4 + 1][r] = av.y;
        As[c4 + 2][r] = av.z; As[c4 + 3][r] = av.w;
        Bs[c4 + 0][r] = bv.x; Bs[c4 + 1][r] = bv.y;
        Bs[c4 + 2][r] = bv.z; Bs[c4 + 3][r] = bv.w;
        __syncthreads();
        if (k0 + 8 < HD_) {
            av = *(const float4*)(Ap + k0 + 8);
            bv = *(const float4*)(Bp + k0 + 8);
        }
        #pragma unroll
        for (int k = 0; k < 8; k++) {
            float a[8], bb[8];
            *(float4*)&a[0]  = *(const float4*)&As[k][ty * 8];
            *(float4*)&a[4]  = *(const float4*)&As[k][ty * 8 + 4];
            *(float4*)&bb[0] = *(const float4*)&Bs[k][tx * 8];
            *(float4*)&bb[4] = *(const float4*)&Bs[k][tx * 8 + 4];
            #pragma unroll
            for (int i = 0; i < 8; i++) {
                #pragma unroll
                for (int j = 0; j < 8; j++)
                    acc[i][j] = fmaf(a[i], bb[j], acc[i][j]);
            }
        }
    }

    const float scale = 0.08838834764831845f;  // rsqrt(128)
    #pragma unroll
    for (int i = 0; i < 8; i++) {
        const int rr = row0 + ty * 8 + i;
        float v[8];
        #pragma unroll
        for (int j = 0; j < 8; j++) v[j] = acc[i][j] * scale;
        float* cp = sb + (size_t)rr * S_ + col0 + tx * 8;
        *(float4*)cp       = *(float4*)&v[0];
        *(float4*)(cp + 4) = *(float4*)&v[4];
    }
}

// ---------------- causal softmax over one row, zero-fill to tile boundary ---
__global__ __launch_bounds__(256)
void softmax_causal(float* __restrict__ scores)
{
    const int q = blockIdx.x;
    const int z = blockIdx.y;
    float* row = scores + (size_t)z * S_ * S_ + (size_t)q * S_;
    const int len = q + 1;
    const int kend = ((q >> 7) + 1) << 7;  // round up to 128 multiple
    const int t = threadIdx.x;

    float r[8];
    float mx = -1e30f;
    #pragma unroll
    for (int i = 0; i < 8; i++) {
        const int k = t + i * 256;
        r[i] = (k < len) ? row[k] : -1e30f;
        mx = fmaxf(mx, r[i]);
    }
    __shared__ float sh[256];
    sh[t] = mx;
    __syncthreads();
    #pragma unroll
    for (int o = 128; o > 0; o >>= 1) {
        if (t < o) sh[t] = fmaxf(sh[t], sh[t + o]);
        __syncthreads();
    }
    mx = sh[0];
    __syncthreads();

    float sum = 0.f;
    #pragma unroll
    for (int i = 0; i < 8; i++) {
        const int k = t + i * 256;
        if (k < len) { r[i] = expf(r[i] - mx); sum += r[i]; }
        else r[i] = 0.f;
    }
    sh[t] = sum;
    __syncthreads();
    #pragma unroll
    for (int o = 128; o > 0; o >>= 1) {
        if (t < o) sh[t] += sh[t + o];
        __syncthreads();
    }
    const float inv = 1.0f / sh[0];

    #pragma unroll
    for (int i = 0; i < 8; i++) {
        const int k = t + i * 256;
        if (k < len)       row[k] = r[i] * inv;
        else if (k < kend) row[k] = 0.f;
    }
}

// ---------------- attn = W @ V per (b,h), K bounded by causal tile ----------
// grid: (16 q-tiles, B*H). N = HD = 128.
__global__ __launch_bounds__(256)
void attn_av(const float* __restrict__ qkv, const float* __restrict__ scores,
             float* __restrict__ attn)
{
    const int qt = blockIdx.x;
    const int z = blockIdx.y;
    const int b = z >> 4, hh = z & 15;

    const float* W = scores + (size_t)z * S_ * S_;
    const float* V = qkv + (size_t)b * S_ * QKVLD + 2 * E_ + hh * HD_;
    float* Cb = attn + (size_t)b * S_ * E_ + hh * HD_;

    __shared__ __align__(16) float As[8][128];
    __shared__ __align__(16) float Bs[8][128];

    const int t = threadIdx.x;
    const int arow = t >> 1;
    const int acol = (t & 1) * 4;
    const int brow = t >> 5;
    const int bcol = (t & 31) * 4;
    const int tx = t & 15;
    const int ty = t >> 4;
    const int row0 = qt * 128;
    const int Kend = (qt + 1) * 128;

    const float* Ap = W + (size_t)(row0 + arow) * S_ + acol;
    const float* Bp = V + (size_t)brow * QKVLD + bcol;

    float acc[8][8];
    #pragma unroll
    for (int i = 0; i < 8; i++) {
        #pragma unroll
        for (int j = 0; j < 8; j++) acc[i][j] = 0.f;
    }

    float4 av = *(const float4*)Ap;
    float4 bv = *(const float4*)Bp;

    for (int k0 = 0; k0 < Kend; k0 += 8) {
        __syncthreads();
        As[acol + 0][arow] = av.x;
        As[acol + 1][arow] = av.y;
        As[acol + 2][arow] = av.z;
        As[acol + 3][arow] = av.w;
        *(float4*)&Bs[brow][bcol] = bv;
        __syncthreads();
        if (k0 + 8 < Kend) {
            av = *(const float4*)(Ap + k0 + 8);
            bv = *(const float4*)(Bp + (size_t)(k0 + 8) * QKVLD);
        }
        #pragma unroll
        for (int k = 0; k < 8; k++) {
            float a[8], bb[8];
            *(float4*)&a[0]  = *(const float4*)&As[k][ty * 8];
            *(float4*)&a[4]  = *(const float4*)&As[k][ty * 8 + 4];
            *(float4*)&bb[0] = *(const float4*)&Bs[k][tx * 8];
            *(float4*)&bb[4] = *(const float4*)&Bs[k][tx * 8 + 4];
            #pragma unroll
            for (int i = 0; i < 8; i++) {
                #pragma unroll
                for (int j = 0; j < 8; j++)
                    acc[i][j] = fmaf(a[i], bb[j], acc[i][j]);
            }
        }
    }

    #pragma unroll
    for (int i = 0; i < 8; i++) {
        const int rr = row0 + ty * 8 + i;
        float* cp = Cb + (size_t)rr * E_ + tx * 8;
        *(float4*)cp       = *(float4*)&acc[i][0];
        *(float4*)(cp + 4) = *(float4*)&acc[i][4];
    }
}

// ---------------- launch --------------------------------------------------
extern "C" void kernel_launch(void* const* d_in, const int* in_sizes, int n_in,
                              void* d_out, int out_size)
{
    const float* x     = (const float*)d_in[0];
    // d_in[1] = mask (tril) — causality implemented directly
    const float* ln1_g = (const float*)d_in[2];
    const float* ln1_b = (const float*)d_in[3];
    const float* Wqkv  = (const float*)d_in[4];
    const float* bqkv  = (const float*)d_in[5];
    const float* Wo    = (const float*)d_in[6];
    const float* bo    = (const float*)d_in[7];
    const float* ln2_g = (const float*)d_in[8];
    const float* ln2_b = (const float*)d_in[9];
    const float* Wfc   = (const float*)d_in[10];
    const float* bfc   = (const float*)d_in[11];
    const float* Wp    = (const float*)d_in[12];
    const float* bp    = (const float*)d_in[13];
    float* out = (float*)d_out;

    float *h, *qkv, *scores, *attn, *x2, *ff;
    cudaGetSymbolAddress((void**)&h, g_h);
    cudaGetSymbolAddress((void**)&qkv, g_qkv);
    cudaGetSymbolAddress((void**)&scores, g_scores);
    cudaGetSymbolAddress((void**)&attn, g_attn);
    cudaGetSymbolAddress((void**)&x2, g_x2);
    cudaGetSymbolAddress((void**)&ff, g_ff);

    // 1. LN1
    ln_kernel<<<NTOK, 256>>>(x, ln1_g, ln1_b, h);
    // 2. qkv = h @ Wqkv + bqkv   [8192 x 6144]
    sgemm_nn<1><<<dim3(QKVLD / 128, NTOK / 128), 256>>>(
        h, E_, Wqkv, QKVLD, qkv, QKVLD, bqkv, nullptr, 0, E_);
    // 3. scores = scale * Q K^T (causal lower-triangle blocks only)
    attn_scores<<<dim3(16, 16, B_ * H_), 256>>>(qkv, scores);
    // 4. causal softmax (zero-fills to 128-boundary for step 5)
    softmax_causal<<<dim3(S_, B_ * H_), 256>>>(scores);
    // 5. attn = W @ V  → [b, q, h*HD]
    attn_av<<<dim3(16, B_ * H_), 256>>>(qkv, scores, attn);
    // 6. x2 = x + attn @ Wo + bo
    sgemm_nn<3><<<dim3(E_ / 128, NTOK / 128), 256>>>(
        attn, E_, Wo, E_, x2, E_, bo, x, E_, E_);
    // 7. LN2
    ln_kernel<<<NTOK, 256>>>(x2, ln2_g, ln2_b, h);
    // 8. ff = gelu(h2 @ Wfc + bfc)   [8192 x 8192]
    sgemm_nn<2><<<dim3(M_ / 128, NTOK / 128), 256>>>(
        h, E_, Wfc, M_, ff, M_, bfc, nullptr, 0, E_);
    // 9. out = x2 + ff @ Wp + bp
    sgemm_nn<3><<<dim3(E_ / 128, NTOK / 128), 256>>>(
        ff, M_, Wp, E_, out, E_, bp, x2, E_, M_);
}